// round 15
// baseline (speedup 1.0000x reference)
#include <cuda_runtime.h>
#include <stdint.h>

#define NTHREADS 256
#define TOK_PER_CTA 8

__device__ __forceinline__ float silu_fast(float x) {
    return __fdividef(x, 1.0f + __expf(-x));   // MUFU.EX2 + MUFU.RCP
}
// rint (half-to-even == jnp.round) then clamp in float domain.
__device__ __forceinline__ float quantf(float a, float inv_scale) {
    return fminf(fmaxf(rintf(a * inv_scale), -127.0f), 127.0f);
}
__device__ __forceinline__ int quanti(float a, float inv_scale) {
    int q = __float2int_rn(a * inv_scale);
    return max(-127, min(127, q));
}
__device__ __forceinline__ float amax4(float cur, float4 a) {
    return fmaxf(cur, fmaxf(fmaxf(fabsf(a.x), fabsf(a.y)),
                            fmaxf(fabsf(a.z), fabsf(a.w))));
}

// 8 contiguous tokens per CTA with rolling register prefetch:
//   - next token's gate/up DRAM loads are in flight during the current
//     token's reduce/store tail (covers 7/8 of tails),
//   - CTA lifetime (~8 iterations, grid=2048 ≈ 2.3 waves) stays short enough
//     for HW wave rebalancing (18-iteration persistent CTAs showed 1.5-2x
//     straggler spread in the timed loop; 4-iteration CTAs did not).
// smooth_scale is a 64KB L1-resident table -> loaded at use time.
template <int D4PER, bool OUT_FLOAT>
__global__ __launch_bounds__(NTHREADS, 6)
void swiglu_quant_roll8(const float* __restrict__ input,
                        const float* __restrict__ smooth_scale,
                        const int*   __restrict__ sorted_ids,
                        const int*   __restrict__ topk,
                        void*        __restrict__ qout,
                        float*       __restrict__ qscale,
                        int d, int N)
{
    const int t     = threadIdx.x;
    int token       = blockIdx.x * TOK_PER_CTA;
    if (token >= N) return;
    const int tokEnd = min(token + TOK_PER_CTA, N);

    __shared__ float wmax[2][NTHREADS / 32];

    // Prologue: prefetch first token's gate/up into registers.
    int sid = __ldg(sorted_ids + token);
    float4 G[D4PER], U[D4PER];
    {
        const float4* g = reinterpret_cast<const float4*>(input + (size_t)sid * (size_t)(2 * d));
        const float4* u = g + (d >> 2);
        #pragma unroll
        for (int k = 0; k < D4PER; k++) {
            const int i = t + k * NTHREADS;
            G[k] = __ldg(g + i);
            U[k] = __ldg(u + i);
        }
    }
    int next = token + 1;
    int sid_next = (next < tokEnd) ? __ldg(sorted_ids + next) : 0;

    int parity = 0;
    while (true) {
        const int e = __ldg(topk + token);
        const float4* ss = reinterpret_cast<const float4*>(smooth_scale + (size_t)e * (size_t)d);

        // act from buffered G/U; S loads are L1 hits.
        float4 A[D4PER];
        float am = 0.0f;
        #pragma unroll
        for (int k = 0; k < D4PER; k++) {
            const int i = t + k * NTHREADS;
            const float4 S = __ldg(ss + i);
            A[k].x = silu_fast(G[k].x) * U[k].x * S.x;
            A[k].y = silu_fast(G[k].y) * U[k].y * S.y;
            A[k].z = silu_fast(G[k].z) * U[k].z * S.z;
            A[k].w = silu_fast(G[k].w) * U[k].w * S.w;
            am = amax4(am, A[k]);
        }

        // Issue NEXT token's DRAM loads now — in flight through reduce/store.
        if (next < tokEnd) {
            const float4* g2 = reinterpret_cast<const float4*>(input + (size_t)sid_next * (size_t)(2 * d));
            const float4* u2 = g2 + (d >> 2);
            #pragma unroll
            for (int k = 0; k < D4PER; k++) {
                const int i = t + k * NTHREADS;
                G[k] = __ldg(g2 + i);
                U[k] = __ldg(u2 + i);
            }
            if (next + 1 < tokEnd) sid_next = __ldg(sorted_ids + next + 1);
        }

        // Block amax reduce (one barrier; wmax parity double-buffered).
        #pragma unroll
        for (int o = 16; o > 0; o >>= 1)
            am = fmaxf(am, __shfl_xor_sync(0xffffffffu, am, o));
        if ((t & 31) == 0) wmax[parity][t >> 5] = am;
        __syncthreads();
        float bmax = wmax[parity][0];
        #pragma unroll
        for (int w = 1; w < NTHREADS / 32; w++) bmax = fmaxf(bmax, wmax[parity][w]);

        const float scale     = (bmax > 0.0f) ? __fdiv_rn(bmax, 127.0f) : 1.0f;
        const float inv_scale = (bmax > 0.0f) ? __fdividef(127.0f, bmax) : 1.0f;
        if (t == 0) qscale[token] = scale;

        if (OUT_FLOAT) {
            float4* orow = reinterpret_cast<float4*>((float*)qout + (size_t)token * (size_t)d);
            #pragma unroll
            for (int k = 0; k < D4PER; k++) {
                const int i = t + k * NTHREADS;
                float4 f;
                f.x = quantf(A[k].x, inv_scale);
                f.y = quantf(A[k].y, inv_scale);
                f.z = quantf(A[k].z, inv_scale);
                f.w = quantf(A[k].w, inv_scale);
                __stcs(orow + i, f);   // streaming store: output never re-read
            }
        } else {
            char4* orow = reinterpret_cast<char4*>((int8_t*)qout + (size_t)token * (size_t)d);
            #pragma unroll
            for (int k = 0; k < D4PER; k++) {
                const int i = t + k * NTHREADS;
                char4 c;
                c.x = (char)quanti(A[k].x, inv_scale);
                c.y = (char)quanti(A[k].y, inv_scale);
                c.z = (char)quanti(A[k].z, inv_scale);
                c.w = (char)quanti(A[k].w, inv_scale);
                orow[i] = c;
            }
        }

        if (next >= tokEnd) break;
        token = next;
        next++;
        parity ^= 1;
    }
}

// Generic fallback for any d (smem-staged act), one CTA per token.
template <bool OUT_FLOAT>
__global__ __launch_bounds__(256, 1)
void swiglu_quant_generic(const float* __restrict__ input,
                          const float* __restrict__ smooth_scale,
                          const int*   __restrict__ sorted_ids,
                          const int*   __restrict__ topk,
                          void*        __restrict__ qout,
                          float*       __restrict__ qscale,
                          int d)
{
    extern __shared__ float s_act[];
    const int token = blockIdx.x;
    const int t     = threadIdx.x;

    const int sid = __ldg(sorted_ids + token);
    const int e   = __ldg(topk + token);

    const float* gate = input + (size_t)sid * (size_t)(2 * d);
    const float* up   = gate + d;
    const float* ss   = smooth_scale + (size_t)e * (size_t)d;

    float amax = 0.0f;
    for (int j = t; j < d; j += blockDim.x) {
        float a = silu_fast(__ldg(gate + j)) * __ldg(up + j) * __ldg(ss + j);
        s_act[j] = a;
        amax = fmaxf(amax, fabsf(a));
    }

    __shared__ float wmax[8];
    #pragma unroll
    for (int o = 16; o > 0; o >>= 1)
        amax = fmaxf(amax, __shfl_xor_sync(0xffffffffu, amax, o));
    if ((t & 31) == 0) wmax[t >> 5] = amax;
    __syncthreads();
    float bmax = wmax[0];
    #pragma unroll
    for (int w = 1; w < 8; w++) bmax = fmaxf(bmax, wmax[w]);

    const float scale     = (bmax > 0.0f) ? __fdiv_rn(bmax, 127.0f) : 1.0f;
    const float inv_scale = (bmax > 0.0f) ? __fdividef(127.0f, bmax) : 1.0f;
    if (t == 0) qscale[token] = scale;

    if (OUT_FLOAT) {
        float* orow = (float*)qout + (size_t)token * (size_t)d;
        for (int j = t; j < d; j += blockDim.x)
            orow[j] = quantf(s_act[j], inv_scale);
    } else {
        int8_t* orow = (int8_t*)qout + (size_t)token * (size_t)d;
        for (int j = t; j < d; j += blockDim.x)
            orow[j] = (int8_t)quanti(s_act[j], inv_scale);
    }
}

extern "C" void kernel_launch(void* const* d_in, const int* in_sizes, int n_in,
                              void* d_out, int out_size)
{
    const float* input        = (const float*)d_in[0];
    const float* smooth_scale = (const float*)d_in[1];
    const int*   sorted_ids   = (const int*)d_in[2];
    const int*   topk         = (const int*)d_in[3];

    const int N   = in_sizes[2];             // tokens (16384)
    const int fc1 = in_sizes[0] / N;         // 4096
    const int d   = fc1 / 2;                 // 2048

    // Output packing (f32 common dtype confirmed in R3/R4):
    const long long want_f32 = (long long)N * d + N;
    const bool out_float = ((long long)out_size == want_f32);

    void*  qout   = d_out;
    float* qscale = out_float
        ? ((float*)d_out + (size_t)N * (size_t)d)
        : (float*)((int8_t*)d_out + (size_t)N * (size_t)d);

    const int per = d / (4 * NTHREADS);      // float4s per thread per half (2 for d=2048)
    const bool fast = (d % (4 * NTHREADS) == 0) && per >= 1 && per <= 2;
    const int grid = (N + TOK_PER_CTA - 1) / TOK_PER_CTA;

    if (fast) {
        if (out_float) {
            if (per == 1) swiglu_quant_roll8<1, true><<<grid, NTHREADS>>>(input, smooth_scale, sorted_ids, topk, qout, qscale, d, N);
            else          swiglu_quant_roll8<2, true><<<grid, NTHREADS>>>(input, smooth_scale, sorted_ids, topk, qout, qscale, d, N);
        } else {
            if (per == 1) swiglu_quant_roll8<1, false><<<grid, NTHREADS>>>(input, smooth_scale, sorted_ids, topk, qout, qscale, d, N);
            else          swiglu_quant_roll8<2, false><<<grid, NTHREADS>>>(input, smooth_scale, sorted_ids, topk, qout, qscale, d, N);
        }
    } else {
        if (out_float)
            swiglu_quant_generic<true><<<N, 256, d * sizeof(float)>>>(input, smooth_scale, sorted_ids, topk, qout, qscale, d);
        else
            swiglu_quant_generic<false><<<N, 256, d * sizeof(float)>>>(input, smooth_scale, sorted_ids, topk, qout, qscale, d);
    }
}

// round 16
// speedup vs baseline: 1.0332x; 1.0332x over previous
#include <cuda_runtime.h>
#include <stdint.h>

#define NTHREADS 256
#define TOK_PER_CTA 4   // measured optimum: 2->54.3, 4->52.0, 8->55.0, persistent->50.9 (bad e2e)

__device__ __forceinline__ float silu_fast(float x) {
    return __fdividef(x, 1.0f + __expf(-x));   // MUFU.EX2 + MUFU.RCP
}
// rint (half-to-even == jnp.round) then clamp in float domain.
__device__ __forceinline__ float quantf(float a, float inv_scale) {
    return fminf(fmaxf(rintf(a * inv_scale), -127.0f), 127.0f);
}
__device__ __forceinline__ int quanti(float a, float inv_scale) {
    int q = __float2int_rn(a * inv_scale);
    return max(-127, min(127, q));
}
__device__ __forceinline__ float amax4(float cur, float4 a) {
    return fmaxf(cur, fmaxf(fmaxf(fabsf(a.x), fabsf(a.y)),
                            fmaxf(fabsf(a.z), fabsf(a.w))));
}

// 4 contiguous tokens per CTA with rolling register prefetch:
//   - the next token's gate/up DRAM loads are issued before the current
//     token's reduce/store tail (ptxas keeps LDGs ahead of BAR.SYNC), so the
//     DRAM pipe stays fed through 3/4 of the otherwise load-free tails;
//   - CTA lifetime (4 iterations, grid = 4096 ≈ 4.6 waves) is short enough
//     for HW wave rebalancing — longer-lived CTAs (8/persistent) measured
//     WORSE e2e due to partial-wave tails and straggler spread.
// smooth_scale (64KB) is L1-resident -> loaded at use time, never prefetched.
template <int D4PER, bool OUT_FLOAT>
__global__ __launch_bounds__(NTHREADS, 6)
void swiglu_quant_roll4(const float* __restrict__ input,
                        const float* __restrict__ smooth_scale,
                        const int*   __restrict__ sorted_ids,
                        const int*   __restrict__ topk,
                        void*        __restrict__ qout,
                        float*       __restrict__ qscale,
                        int d, int N)
{
    const int t     = threadIdx.x;
    int token       = blockIdx.x * TOK_PER_CTA;
    if (token >= N) return;
    const int tokEnd = min(token + TOK_PER_CTA, N);

    __shared__ float wmax[2][NTHREADS / 32];

    // Prologue: prefetch first token's gate/up into registers.
    int sid = __ldg(sorted_ids + token);
    float4 G[D4PER], U[D4PER];
    {
        const float4* g = reinterpret_cast<const float4*>(input + (size_t)sid * (size_t)(2 * d));
        const float4* u = g + (d >> 2);
        #pragma unroll
        for (int k = 0; k < D4PER; k++) {
            const int i = t + k * NTHREADS;
            G[k] = __ldg(g + i);
            U[k] = __ldg(u + i);
        }
    }
    int next = token + 1;
    int sid_next = (next < tokEnd) ? __ldg(sorted_ids + next) : 0;

    int parity = 0;
    while (true) {
        const int e = __ldg(topk + token);
        const float4* ss = reinterpret_cast<const float4*>(smooth_scale + (size_t)e * (size_t)d);

        // act from buffered G/U; S loads are L1 hits.
        float4 A[D4PER];
        float am = 0.0f;
        #pragma unroll
        for (int k = 0; k < D4PER; k++) {
            const int i = t + k * NTHREADS;
            const float4 S = __ldg(ss + i);
            A[k].x = silu_fast(G[k].x) * U[k].x * S.x;
            A[k].y = silu_fast(G[k].y) * U[k].y * S.y;
            A[k].z = silu_fast(G[k].z) * U[k].z * S.z;
            A[k].w = silu_fast(G[k].w) * U[k].w * S.w;
            am = amax4(am, A[k]);
        }

        // Issue NEXT token's DRAM loads now — in flight through reduce/store.
        if (next < tokEnd) {
            const float4* g2 = reinterpret_cast<const float4*>(input + (size_t)sid_next * (size_t)(2 * d));
            const float4* u2 = g2 + (d >> 2);
            #pragma unroll
            for (int k = 0; k < D4PER; k++) {
                const int i = t + k * NTHREADS;
                G[k] = __ldg(g2 + i);
                U[k] = __ldg(u2 + i);
            }
            if (next + 1 < tokEnd) sid_next = __ldg(sorted_ids + next + 1);
        }

        // Block amax reduce (one barrier; wmax parity double-buffered).
        #pragma unroll
        for (int o = 16; o > 0; o >>= 1)
            am = fmaxf(am, __shfl_xor_sync(0xffffffffu, am, o));
        if ((t & 31) == 0) wmax[parity][t >> 5] = am;
        __syncthreads();
        float bmax = wmax[parity][0];
        #pragma unroll
        for (int w = 1; w < NTHREADS / 32; w++) bmax = fmaxf(bmax, wmax[parity][w]);

        const float scale     = (bmax > 0.0f) ? __fdiv_rn(bmax, 127.0f) : 1.0f;   // exact, matches ref
        const float inv_scale = (bmax > 0.0f) ? __fdividef(127.0f, bmax) : 1.0f;  // fast, hoisted
        if (t == 0) qscale[token] = scale;

        if (OUT_FLOAT) {
            float4* orow = reinterpret_cast<float4*>((float*)qout + (size_t)token * (size_t)d);
            #pragma unroll
            for (int k = 0; k < D4PER; k++) {
                const int i = t + k * NTHREADS;
                float4 f;
                f.x = quantf(A[k].x, inv_scale);
                f.y = quantf(A[k].y, inv_scale);
                f.z = quantf(A[k].z, inv_scale);
                f.w = quantf(A[k].w, inv_scale);
                __stcs(orow + i, f);   // streaming store: output never re-read
            }
        } else {
            char4* orow = reinterpret_cast<char4*>((int8_t*)qout + (size_t)token * (size_t)d);
            #pragma unroll
            for (int k = 0; k < D4PER; k++) {
                const int i = t + k * NTHREADS;
                char4 c;
                c.x = (char)quanti(A[k].x, inv_scale);
                c.y = (char)quanti(A[k].y, inv_scale);
                c.z = (char)quanti(A[k].z, inv_scale);
                c.w = (char)quanti(A[k].w, inv_scale);
                orow[i] = c;
            }
        }

        if (next >= tokEnd) break;
        token = next;
        next++;
        parity ^= 1;
    }
}

// Generic fallback for any d (smem-staged act), one CTA per token.
template <bool OUT_FLOAT>
__global__ __launch_bounds__(256, 1)
void swiglu_quant_generic(const float* __restrict__ input,
                          const float* __restrict__ smooth_scale,
                          const int*   __restrict__ sorted_ids,
                          const int*   __restrict__ topk,
                          void*        __restrict__ qout,
                          float*       __restrict__ qscale,
                          int d)
{
    extern __shared__ float s_act[];
    const int token = blockIdx.x;
    const int t     = threadIdx.x;

    const int sid = __ldg(sorted_ids + token);
    const int e   = __ldg(topk + token);

    const float* gate = input + (size_t)sid * (size_t)(2 * d);
    const float* up   = gate + d;
    const float* ss   = smooth_scale + (size_t)e * (size_t)d;

    float amax = 0.0f;
    for (int j = t; j < d; j += blockDim.x) {
        float a = silu_fast(__ldg(gate + j)) * __ldg(up + j) * __ldg(ss + j);
        s_act[j] = a;
        amax = fmaxf(amax, fabsf(a));
    }

    __shared__ float wmax[8];
    #pragma unroll
    for (int o = 16; o > 0; o >>= 1)
        amax = fmaxf(amax, __shfl_xor_sync(0xffffffffu, amax, o));
    if ((t & 31) == 0) wmax[t >> 5] = amax;
    __syncthreads();
    float bmax = wmax[0];
    #pragma unroll
    for (int w = 1; w < 8; w++) bmax = fmaxf(bmax, wmax[w]);

    const float scale     = (bmax > 0.0f) ? __fdiv_rn(bmax, 127.0f) : 1.0f;
    const float inv_scale = (bmax > 0.0f) ? __fdividef(127.0f, bmax) : 1.0f;
    if (t == 0) qscale[token] = scale;

    if (OUT_FLOAT) {
        float* orow = (float*)qout + (size_t)token * (size_t)d;
        for (int j = t; j < d; j += blockDim.x)
            orow[j] = quantf(s_act[j], inv_scale);
    } else {
        int8_t* orow = (int8_t*)qout + (size_t)token * (size_t)d;
        for (int j = t; j < d; j += blockDim.x)
            orow[j] = (int8_t)quanti(s_act[j], inv_scale);
    }
}

extern "C" void kernel_launch(void* const* d_in, const int* in_sizes, int n_in,
                              void* d_out, int out_size)
{
    const float* input        = (const float*)d_in[0];
    const float* smooth_scale = (const float*)d_in[1];
    const int*   sorted_ids   = (const int*)d_in[2];
    const int*   topk         = (const int*)d_in[3];

    const int N   = in_sizes[2];             // tokens (16384)
    const int fc1 = in_sizes[0] / N;         // 4096
    const int d   = fc1 / 2;                 // 2048

    // Output packing (f32 common dtype confirmed in R3/R4):
    const long long want_f32 = (long long)N * d + N;
    const bool out_float = ((long long)out_size == want_f32);

    void*  qout   = d_out;
    float* qscale = out_float
        ? ((float*)d_out + (size_t)N * (size_t)d)
        : (float*)((int8_t*)d_out + (size_t)N * (size_t)d);

    const int per = d / (4 * NTHREADS);      // float4s per thread per half (2 for d=2048)
    const bool fast = (d % (4 * NTHREADS) == 0) && per >= 1 && per <= 2;
    const int grid = (N + TOK_PER_CTA - 1) / TOK_PER_CTA;

    if (fast) {
        if (out_float) {
            if (per == 1) swiglu_quant_roll4<1, true><<<grid, NTHREADS>>>(input, smooth_scale, sorted_ids, topk, qout, qscale, d, N);
            else          swiglu_quant_roll4<2, true><<<grid, NTHREADS>>>(input, smooth_scale, sorted_ids, topk, qout, qscale, d, N);
        } else {
            if (per == 1) swiglu_quant_roll4<1, false><<<grid, NTHREADS>>>(input, smooth_scale, sorted_ids, topk, qout, qscale, d, N);
            else          swiglu_quant_roll4<2, false><<<grid, NTHREADS>>>(input, smooth_scale, sorted_ids, topk, qout, qscale, d, N);
        }
    } else {
        if (out_float)
            swiglu_quant_generic<true><<<N, 256, d * sizeof(float)>>>(input, smooth_scale, sorted_ids, topk, qout, qscale, d);
        else
            swiglu_quant_generic<false><<<N, 256, d * sizeof(float)>>>(input, smooth_scale, sorted_ids, topk, qout, qscale, d);
    }
}